// round 1
// baseline (speedup 1.0000x reference)
#include <cuda_runtime.h>
#include <math.h>

// Problem constants (fixed by the seeded reference):
//   m=8, nc=1024, nt=512, dim=2, dy=2, PPU=64, N=64 per dim -> axes of 129.
#define M_B   8
#define NC    1024
#define NT    512
#define AX    129
#define NG    (AX * AX)            // 16641 grid points per batch
#define HALF  64
#define INV_PPU (1.0f / 64.0f)
#define X_TOTAL (M_B * NG * 2)     // 266256 floats of x_grid, then z_grid

// Scratch (no allocations allowed): scaled contexts + per-batch grid midpoints.
__device__ float4 g_ctx[M_B * NC];   // {xc0*k0, xc1*k1, yc0, yc1}
__device__ float2 g_mid[M_B];

__device__ __forceinline__ float ex2f(float x) {
    float r;
    asm("ex2.approx.f32 %0, %1;" : "=f"(r) : "f"(x));
    return r;
}

__device__ __forceinline__ float soft_k(float p) {
    // k = sqrt(0.5*log2(e)) / (1e-5 + softplus(p)); weight = 2^(-sum((dx*k)^2))
    float ls = 1e-5f + log1pf(expf(p));
    return sqrtf(0.5f * 1.44269504088896341f) / ls;
}

// Kernel 1: per-batch min/max over concat(xc, xt) -> mid; scale contexts.
__global__ void __launch_bounds__(256) prep_kernel(const float* __restrict__ xc,
                                                   const float* __restrict__ yc,
                                                   const float* __restrict__ xt,
                                                   const float* __restrict__ lsp) {
    const int b = blockIdx.x;
    const int t = threadIdx.x;
    const float* xb = xc + b * NC * 2;
    const float* tb = xt + b * NT * 2;
    const float* yb = yc + b * NC * 2;

    float mn0 = 1e30f, mx0 = -1e30f, mn1 = 1e30f, mx1 = -1e30f;
    for (int i = t; i < NC; i += 256) {
        float a = xb[2 * i], c = xb[2 * i + 1];
        mn0 = fminf(mn0, a); mx0 = fmaxf(mx0, a);
        mn1 = fminf(mn1, c); mx1 = fmaxf(mx1, c);
    }
    for (int i = t; i < NT; i += 256) {
        float a = tb[2 * i], c = tb[2 * i + 1];
        mn0 = fminf(mn0, a); mx0 = fmaxf(mx0, a);
        mn1 = fminf(mn1, c); mx1 = fmaxf(mx1, c);
    }
    // warp reduce
    for (int o = 16; o; o >>= 1) {
        mn0 = fminf(mn0, __shfl_xor_sync(0xffffffffu, mn0, o));
        mx0 = fmaxf(mx0, __shfl_xor_sync(0xffffffffu, mx0, o));
        mn1 = fminf(mn1, __shfl_xor_sync(0xffffffffu, mn1, o));
        mx1 = fmaxf(mx1, __shfl_xor_sync(0xffffffffu, mx1, o));
    }
    __shared__ float s[4][8];
    const int lane = t & 31, wid = t >> 5;
    if (lane == 0) { s[0][wid] = mn0; s[1][wid] = mx0; s[2][wid] = mn1; s[3][wid] = mx1; }
    __syncthreads();
    if (t == 0) {
        float a = s[0][0], bb = s[1][0], c = s[2][0], d = s[3][0];
        #pragma unroll
        for (int w = 1; w < 8; w++) {
            a = fminf(a, s[0][w]); bb = fmaxf(bb, s[1][w]);
            c = fminf(c, s[2][w]); d = fmaxf(d, s[3][w]);
        }
        g_mid[b] = make_float2(0.5f * (a + bb), 0.5f * (c + d));
    }

    const float k0 = soft_k(lsp[0]);
    const float k1 = soft_k(lsp[1]);
    for (int i = t; i < NC; i += 256) {
        g_ctx[b * NC + i] = make_float4(xb[2 * i] * k0, xb[2 * i + 1] * k1,
                                        yb[2 * i], yb[2 * i + 1]);
    }
}

// Kernel 2: one thread per grid point; loop all 1024 contexts from smem.
__global__ void __launch_bounds__(256) setconv_kernel(const float* __restrict__ lsp,
                                                      float* __restrict__ out) {
    __shared__ float4 sctx[NC];
    const int b = blockIdx.y;
    for (int i = threadIdx.x; i < NC; i += 256) sctx[i] = g_ctx[b * NC + i];
    __syncthreads();

    const int g = blockIdx.x * 256 + threadIdx.x;
    if (g >= NG) return;

    const float2 mid = g_mid[b];
    const int i = g / AX;
    const int j = g - i * AX;
    const float gx = mid.x + (float)(i - HALF) * INV_PPU;
    const float gy = mid.y + (float)(j - HALF) * INV_PPU;

    // x_grid output (bit-exact vs reference)
    float* xg = out + (size_t)(b * NG + g) * 2;
    xg[0] = gx; xg[1] = gy;

    const float k0 = soft_k(lsp[0]);
    const float k1 = soft_k(lsp[1]);
    const float ax = gx * k0;
    const float ay = gy * k1;

    float a0 = 0.0f, a1 = 0.0f, ad = 0.0f;
    #pragma unroll 8
    for (int c = 0; c < NC; c++) {
        const float4 v = sctx[c];
        const float dx = ax - v.x;
        const float dy = ay - v.y;
        float t = fmaf(dx, -dx, 0.0f);
        t = fmaf(dy, -dy, t);                 // t = -(dx^2 + dy^2), already log2-scaled
        const float w = ex2f(t);              // exp(-0.5*dist2/ls^2)
        a0 = fmaf(w, v.z, a0);
        a1 = fmaf(w, v.w, a1);
        ad += w;
    }

    float* zg = out + X_TOTAL + (size_t)(b * NG + g) * 3;
    zg[0] = a0; zg[1] = a1; zg[2] = ad;
}

extern "C" void kernel_launch(void* const* d_in, const int* in_sizes, int n_in,
                              void* d_out, int out_size) {
    const float* xc  = (const float*)d_in[0];
    const float* yc  = (const float*)d_in[1];
    const float* xt  = (const float*)d_in[2];
    const float* lsp = (const float*)d_in[3];
    float* out = (float*)d_out;

    prep_kernel<<<M_B, 256>>>(xc, yc, xt, lsp);
    dim3 grid((NG + 255) / 256, M_B);
    setconv_kernel<<<grid, 256>>>(lsp, out);
}